// round 1
// baseline (speedup 1.0000x reference)
#include <cuda_runtime.h>
#include <math.h>

#define NB 4
#define NC 256
#define HWP 25600
#define NS 1024
#define NCH 25

// ---------- scratch (static device globals; no allocation) ----------
__device__ float d_G[NB*NC*NS];     // gathered feats, [b][c][s]
__device__ float d_H[NB*NC*NS];     // hidden,        [b][n][s]
__device__ float d_P[NB*NC*NS];     // proj -> fn,    [b][n][s]
__device__ float d_attn[NB*NS];
__device__ int   d_idx[NB*NS];
__device__ int   d_selflag[NB*NS];
__device__ int   d_spv[NB*NS];
__device__ int   d_cntV[NB*32];
__device__ int   d_offV[NB*32];
__device__ int   d_totV[NB];
__device__ int   d_vlist[NB*NS];
__device__ int   d_ilist[NB*NS];
__device__ float d_rowA[NB*NS];
__device__ float d_rowB[NB*NS];
__device__ float d_rowD[NB*NS];

// ---------- zero accumulators (graph replays!) ----------
__global__ void k_zero() {
    int i = blockIdx.x * 1024 + threadIdx.x;
    if (i < NB*NS) { d_rowA[i] = 0.f; d_rowB[i] = 0.f; d_rowD[i] = 0.f; }
}

// ---------- selection: count valid per 1024-chunk ----------
__global__ void k_count(const long long* __restrict__ labels) {
    int ch = blockIdx.x, b = blockIdx.y, t = threadIdx.x;
    const long long* lb = labels + (long long)b*HWP + ch*1024;
    int cnt = 0;
    #pragma unroll
    for (int r = 0; r < 4; r++) cnt += (lb[t*4+r] == 1);
    __shared__ int sh[256];
    sh[t] = cnt; __syncthreads();
    for (int o = 128; o > 0; o >>= 1) { if (t < o) sh[t] += sh[t+o]; __syncthreads(); }
    if (t == 0) d_cntV[b*32+ch] = sh[0];
}

// ---------- scan chunk counts ----------
__global__ void k_scan() {
    int b = blockIdx.x, t = threadIdx.x; // 32 threads
    int v = (t < NCH) ? d_cntV[b*32+t] : 0;
    int incl = v;
    #pragma unroll
    for (int o = 1; o < 32; o <<= 1) {
        int n = __shfl_up_sync(0xffffffffu, incl, o);
        if (t >= o) incl += n;
    }
    if (t < NCH) d_offV[b*32+t] = incl - v;
    if (t == NCH-1) d_totV[b] = incl;
}

// ---------- fill valid/invalid index lists ----------
__global__ void k_fill(const long long* __restrict__ labels) {
    int ch = blockIdx.x, b = blockIdx.y, t = threadIdx.x;
    const long long* lb = labels + (long long)b*HWP + ch*1024;
    int flags[4]; int cnt = 0;
    #pragma unroll
    for (int r = 0; r < 4; r++) { flags[r] = (lb[t*4+r] == 1); cnt += flags[r]; }
    int lane = t & 31, w = t >> 5;
    int incl = cnt;
    #pragma unroll
    for (int o = 1; o < 32; o <<= 1) {
        int n = __shfl_up_sync(0xffffffffu, incl, o);
        if (lane >= o) incl += n;
    }
    __shared__ int wsum[8];
    if (lane == 31) wsum[w] = incl;
    __syncthreads();
    if (t == 0) { int run = 0; for (int i = 0; i < 8; i++) { int x = wsum[i]; wsum[i] = run; run += x; } }
    __syncthreads();
    int excl = incl - cnt + wsum[w];
    int vbase = d_offV[b*32+ch] + excl;
    int pbase = ch*1024 + t*4;
    int vloc = 0;
    #pragma unroll
    for (int r = 0; r < 4; r++) {
        int p = pbase + r;
        if (flags[r]) {
            int vr = vbase + vloc; vloc++;
            if (vr < NS) d_vlist[b*NS+vr] = p;
        } else {
            int Vp = vbase + vloc;          // #valid strictly before p
            int ir = p - Vp;                // invalid rank
            if (ir < NS) d_ilist[b*NS+ir] = p;
        }
    }
}

// ---------- compose idx/sel/sp ----------
__global__ void k_compose(const long long* __restrict__ sp) {
    int b = blockIdx.x, t = threadIdx.x;
    int nv = d_totV[b]; if (nv > NS) nv = NS;
    for (int it = 0; it < 4; it++) {
        int s = it*256 + t;
        int p, sel;
        if (s < nv) { p = d_vlist[b*NS+s]; sel = 1; }
        else        { p = d_ilist[b*NS+(s-nv)]; sel = 0; }
        d_idx[b*NS+s] = p;
        d_selflag[b*NS+s] = sel;
        d_spv[b*NS+s] = (int)sp[(long long)b*HWP + p];
    }
}

// ---------- gather feats -> G[b][c][s] ----------
__global__ void k_gather(const float* __restrict__ feats) {
    int t = threadIdx.x;
    int s = blockIdx.x*256 + t;
    int c = blockIdx.y, b = blockIdx.z;
    int p = d_idx[b*NS+s];
    d_G[((b*NC)+c)*NS + s] = feats[((long long)(b*NC)+c)*HWP + p];
}

// ---------- 64x64 tiled SGEMM:  Y[b][n][s] = act(bias[n] + sum_c W[n][c]*X[b][c][s]) ----------
template<bool RELU>
__global__ void k_gemm(const float* __restrict__ W, const float* __restrict__ bias,
                       const float* __restrict__ X, float* __restrict__ Y, int nrows) {
    int b = blockIdx.z;
    const float* Xb = X + b*NC*NS;
    float* Yb = Y + b*nrows*NS;
    int n0 = blockIdx.y*64, s0 = blockIdx.x*64;
    __shared__ float As[16][65], Bs[16][65];
    int t = threadIdx.x, tx = t & 15, ty = t >> 4;
    float acc[4][4] = {};
    for (int kk = 0; kk < NC; kk += 16) {
        for (int e = t; e < 1024; e += 256) { int nl = e >> 4, kc = e & 15; As[kc][nl] = W[(n0+nl)*NC + kk + kc]; }
        for (int e = t; e < 1024; e += 256) { int kc = e >> 6, sl = e & 63; Bs[kc][sl] = Xb[(kk+kc)*NS + s0 + sl]; }
        __syncthreads();
        #pragma unroll
        for (int kc = 0; kc < 16; kc++) {
            float av[4], bv[4];
            #pragma unroll
            for (int r = 0; r < 4; r++) av[r] = As[kc][ty*4+r];
            #pragma unroll
            for (int q = 0; q < 4; q++) bv[q] = Bs[kc][tx*4+q];
            #pragma unroll
            for (int r = 0; r < 4; r++)
                #pragma unroll
                for (int q = 0; q < 4; q++) acc[r][q] = fmaf(av[r], bv[q], acc[r][q]);
        }
        __syncthreads();
    }
    #pragma unroll
    for (int r = 0; r < 4; r++) {
        float bv = bias[n0 + ty*4 + r];
        #pragma unroll
        for (int q = 0; q < 4; q++) {
            float v = acc[r][q] + bv;
            if (RELU) v = fmaxf(v, 0.f);
            Yb[(n0+ty*4+r)*NS + s0 + tx*4 + q] = v;
        }
    }
}

// ---------- fused attention head: sigmoid(wa2 . relu(wa1 x + ba1) + ba2) ----------
__global__ void k_attn(const float* __restrict__ wa1, const float* __restrict__ ba1,
                       const float* __restrict__ wa2, const float* __restrict__ ba2,
                       const float* __restrict__ X) {
    int b = blockIdx.z;
    const float* Xb = X + b*NC*NS;
    int s0 = blockIdx.x*64;
    __shared__ float As[16][65], Bs[16][65], colsum[64];
    int t = threadIdx.x, tx = t & 15, ty = t >> 4;
    float acc[4][4] = {};
    for (int kk = 0; kk < NC; kk += 16) {
        for (int e = t; e < 1024; e += 256) { int nl = e >> 4, kc = e & 15; As[kc][nl] = wa1[nl*NC + kk + kc]; }
        for (int e = t; e < 1024; e += 256) { int kc = e >> 6, sl = e & 63; Bs[kc][sl] = Xb[(kk+kc)*NS + s0 + sl]; }
        __syncthreads();
        #pragma unroll
        for (int kc = 0; kc < 16; kc++) {
            float av[4], bv[4];
            #pragma unroll
            for (int r = 0; r < 4; r++) av[r] = As[kc][ty*4+r];
            #pragma unroll
            for (int q = 0; q < 4; q++) bv[q] = Bs[kc][tx*4+q];
            #pragma unroll
            for (int r = 0; r < 4; r++)
                #pragma unroll
                for (int q = 0; q < 4; q++) acc[r][q] = fmaf(av[r], bv[q], acc[r][q]);
        }
        __syncthreads();
    }
    if (t < 64) colsum[t] = 0.f;
    __syncthreads();
    float part[4] = {0.f, 0.f, 0.f, 0.f};
    #pragma unroll
    for (int r = 0; r < 4; r++) {
        int m = ty*4 + r;
        float wm = wa2[m], bm = ba1[m];
        #pragma unroll
        for (int q = 0; q < 4; q++) {
            float v = fmaxf(acc[r][q] + bm, 0.f);
            part[q] += wm * v;
        }
    }
    #pragma unroll
    for (int q = 0; q < 4; q++) atomicAdd(&colsum[tx*4+q], part[q]);
    __syncthreads();
    if (t < 64) {
        float z = colsum[t] + ba2[0];
        d_attn[b*NS + s0 + t] = 1.f / (1.f + expf(-z));
    }
}

// ---------- L2-normalize columns of P in place ----------
__global__ void k_norm() {
    int t = threadIdx.x;
    int s = blockIdx.x*256 + t;
    int b = blockIdx.y;
    float* Pb = d_P + b*NC*NS;
    float ss = 0.f;
    for (int c = 0; c < NC; c++) { float v = Pb[c*NS + s]; ss = fmaf(v, v, ss); }
    float sc = 1.f / fmaxf(sqrtf(ss), 1e-12f);
    for (int c = 0; c < NC; c++) Pb[c*NS + s] *= sc;
}

// ---------- fused sim + per-row contrastive reductions ----------
__global__ void k_sim() {
    int b = blockIdx.z;
    int i0 = blockIdx.y*64, j0 = blockIdx.x*64;
    const float* fnb = d_P + b*NC*NS;
    __shared__ float As[16][65], Bs[16][65];
    __shared__ int   spI[64], spJ[64], seI[64], seJ[64];
    __shared__ float wI[64], wJ[64];
    int t = threadIdx.x, tx = t & 15, ty = t >> 4;
    if (t < 64)            { spI[t] = d_spv[b*NS+i0+t]; seI[t] = d_selflag[b*NS+i0+t]; wI[t] = d_attn[b*NS+i0+t]; }
    else if (t < 128)      { int u = t-64; spJ[u] = d_spv[b*NS+j0+u]; seJ[u] = d_selflag[b*NS+j0+u]; wJ[u] = d_attn[b*NS+j0+u]; }
    float acc[4][4] = {};
    for (int kk = 0; kk < NC; kk += 16) {
        for (int e = t; e < 1024; e += 256) { int kc = e >> 6, l = e & 63; As[kc][l] = fnb[(kk+kc)*NS + i0 + l]; }
        for (int e = t; e < 1024; e += 256) { int kc = e >> 6, l = e & 63; Bs[kc][l] = fnb[(kk+kc)*NS + j0 + l]; }
        __syncthreads();
        #pragma unroll
        for (int kc = 0; kc < 16; kc++) {
            float av[4], bv[4];
            #pragma unroll
            for (int r = 0; r < 4; r++) av[r] = As[kc][ty*4+r];
            #pragma unroll
            for (int q = 0; q < 4; q++) bv[q] = Bs[kc][tx*4+q];
            #pragma unroll
            for (int r = 0; r < 4; r++)
                #pragma unroll
                for (int q = 0; q < 4; q++) acc[r][q] = fmaf(av[r], bv[q], acc[r][q]);
        }
        __syncthreads();
    }
    float rA[4] = {}, rB[4] = {}, rD[4] = {};
    #pragma unroll
    for (int r = 0; r < 4; r++) {
        int il = ty*4 + r;
        int gi = i0 + il;
        int si = seI[il], spi = spI[il];
        float wi = wI[il];
        #pragma unroll
        for (int q = 0; q < 4; q++) {
            int jl = tx*4 + q;
            int gj = j0 + jl;
            float s = acc[r][q];
            if (seJ[jl]) {
                rD[r] += expf(s * 10.0f);                  // 1/TEMP = 10
                if (si && (gi != gj) && (spi == spJ[jl]) && (s > 0.7f)) {
                    float pw = wi * wJ[jl];
                    rB[r] += pw;
                    rA[r] = fmaf(pw, s, rA[r]);
                }
            }
        }
    }
    // reduce over tx (16-lane groups inside the warp)
    #pragma unroll
    for (int r = 0; r < 4; r++) {
        #pragma unroll
        for (int off = 8; off >= 1; off >>= 1) {
            rA[r] += __shfl_down_sync(0xffffffffu, rA[r], off, 16);
            rB[r] += __shfl_down_sync(0xffffffffu, rB[r], off, 16);
            rD[r] += __shfl_down_sync(0xffffffffu, rD[r], off, 16);
        }
    }
    if (tx == 0) {
        #pragma unroll
        for (int r = 0; r < 4; r++) {
            int gi = i0 + ty*4 + r;
            atomicAdd(&d_rowA[b*NS+gi], rA[r]);
            atomicAdd(&d_rowB[b*NS+gi], rB[r]);
            atomicAdd(&d_rowD[b*NS+gi], rD[r]);
        }
    }
}

// ---------- final reduction ----------
__global__ void k_final(float* __restrict__ out) {
    __shared__ float red[256];
    int t = threadIdx.x;
    float totLoss = 0.f;
    int nHas = 0;
    __shared__ float s_num, s_ps;
    for (int b = 0; b < NB; b++) {
        float num = 0.f, ps = 0.f;
        for (int i = t; i < NS; i += 256) {
            float Ai = d_rowA[b*NS+i], Bi = d_rowB[b*NS+i], Di = d_rowD[b*NS+i];
            float ld = logf(Di > 0.f ? Di : 1.f);
            num += Ai * 10.0f - ld * Bi;   // Ai/TEMP
            ps  += Bi;
        }
        red[t] = num; __syncthreads();
        for (int o = 128; o > 0; o >>= 1) { if (t < o) red[t] += red[t+o]; __syncthreads(); }
        if (t == 0) s_num = red[0];
        __syncthreads();
        red[t] = ps; __syncthreads();
        for (int o = 128; o > 0; o >>= 1) { if (t < o) red[t] += red[t+o]; __syncthreads(); }
        if (t == 0) s_ps = red[0];
        __syncthreads();
        if (t == 0) {
            if (s_ps > 0.f) {
                totLoss += -(0.1f/0.07f) * s_num / s_ps;
                nHas++;
            }
        }
        __syncthreads();
    }
    if (t == 0) out[0] = (nHas > 0) ? (totLoss / fmaxf((float)nHas, 1.f)) : 0.f;
}

extern "C" void kernel_launch(void* const* d_in, const int* in_sizes, int n_in,
                              void* d_out, int out_size) {
    const float*     feats  = (const float*)d_in[0];
    const long long* labels = (const long long*)d_in[1];
    const long long* sp     = (const long long*)d_in[2];
    const float*     w1     = (const float*)d_in[3];
    const float*     b1     = (const float*)d_in[4];
    const float*     w2     = (const float*)d_in[5];
    const float*     b2     = (const float*)d_in[6];
    const float*     wa1    = (const float*)d_in[7];
    const float*     ba1    = (const float*)d_in[8];
    const float*     wa2    = (const float*)d_in[9];
    const float*     ba2    = (const float*)d_in[10];
    float* out = (float*)d_out;

    k_zero<<<4, 1024>>>();
    k_count<<<dim3(NCH, NB), 256>>>(labels);
    k_scan<<<NB, 32>>>();
    k_fill<<<dim3(NCH, NB), 256>>>(labels);
    k_compose<<<NB, 256>>>(sp);
    k_gather<<<dim3(NS/256, NC, NB), 256>>>(feats);

    // get symbol addresses indirectly via device pointers captured at launch:
    // (device globals are directly addressable from kernels; GEMMs take raw pointers)
    static float* pG = nullptr; static float* pH = nullptr; static float* pP = nullptr;
    if (!pG) {
        cudaGetSymbolAddress((void**)&pG, d_G);
        cudaGetSymbolAddress((void**)&pH, d_H);
        cudaGetSymbolAddress((void**)&pP, d_P);
    }

    k_gemm<true ><<<dim3(NS/64, NC/64, NB), 256>>>(w1, b1, pG, pH, NC);
    k_gemm<false><<<dim3(NS/64, NC/64, NB), 256>>>(w2, b2, pH, pP, NC);
    k_attn<<<dim3(NS/64, 1, NB), 256>>>(wa1, ba1, wa2, ba2, pG);
    k_norm<<<dim3(NS/256, NB), 256>>>();
    k_sim<<<dim3(NS/64, NS/64, NB), 256>>>();
    k_final<<<1, 256>>>(out);
}

// round 2
// speedup vs baseline: 1.6107x; 1.6107x over previous
#include <cuda_runtime.h>
#include <math.h>

#define NB 4
#define NC 256
#define HWP 25600
#define NS 1024
#define NT 4096   // NB*NS : all per-sample arrays indexed by col = b*NS + s

// ---------- scratch (static device globals; no allocation) ----------
__device__ float d_G[NC*NT];     // gathered feats   [c][col]
__device__ float d_H[NC*NT];     // hidden           [m][col]
__device__ float d_P[NC*NT];     // projection       [m][col]
__device__ float d_attn[NT];
__device__ float d_rnorm[NT];
__device__ int   d_idx[NT];
__device__ int   d_sel[NT];
__device__ int   d_spv[NT];
__device__ int   d_vlist[NT];
__device__ int   d_ilist[NT];
__device__ float d_rowA[NT];
__device__ float d_rowB[NT];
__device__ float d_rowD[NT];

// ---------- fused selection: count/scan/fill/compose/zero, one block per batch ----------
__global__ void k_prep(const long long* __restrict__ labels, const long long* __restrict__ sp) {
    int b = blockIdx.x, t = threadIdx.x;          // 1024 threads
    const long long* lb = labels + (long long)b*HWP;
    int base = t*25;
    unsigned flags = 0; int cnt = 0;
    #pragma unroll
    for (int j = 0; j < 25; j++) {
        int f = (lb[base+j] == 1);
        flags |= (unsigned)f << j; cnt += f;
    }
    __shared__ int wsum[32];
    __shared__ int s_nv;
    int lane = t & 31, w = t >> 5;
    int incl = cnt;
    #pragma unroll
    for (int o = 1; o < 32; o <<= 1) {
        int n = __shfl_up_sync(0xffffffffu, incl, o);
        if (lane >= o) incl += n;
    }
    if (lane == 31) wsum[w] = incl;
    __syncthreads();
    if (t < 32) {
        int v = wsum[t]; int inc2 = v;
        #pragma unroll
        for (int o = 1; o < 32; o <<= 1) {
            int n = __shfl_up_sync(0xffffffffu, inc2, o);
            if (t >= o) inc2 += n;
        }
        wsum[t] = inc2 - v;          // exclusive warp offsets
        if (t == 31) s_nv = inc2;    // total valid
    }
    __syncthreads();
    int v_run = (incl - cnt) + wsum[w];   // # valid strictly before my range
    #pragma unroll
    for (int j = 0; j < 25; j++) {
        int p = base + j;
        if ((flags >> j) & 1u) {
            if (v_run < NS) d_vlist[b*NS + v_run] = p;
            v_run++;
        } else {
            int ir = p - v_run;             // invalid rank
            if (ir < NS) d_ilist[b*NS + ir] = p;
        }
    }
    __syncthreads();
    int nv = s_nv; if (nv > NS) nv = NS;
    int s = t;
    int p, se;
    if (s < nv) { p = d_vlist[b*NS + s];        se = 1; }
    else        { p = d_ilist[b*NS + (s - nv)]; se = 0; }
    int col = b*NS + s;
    d_idx[col] = p;
    d_sel[col] = se;
    d_spv[col] = (int)sp[(long long)b*HWP + p];
    d_rowA[col] = 0.f; d_rowB[col] = 0.f; d_rowD[col] = 0.f;
}

// ---------- gather feats -> G[c][col] ----------
__global__ void k_gather(const float* __restrict__ feats) {
    int t = threadIdx.x;
    int s = blockIdx.x*256 + t;      // 0..1023
    int b = blockIdx.z;
    int c0 = blockIdx.y*32;
    int col = b*NS + s;
    int p = d_idx[col];
    const float* fb = feats + ((long long)b*NC + c0)*HWP + p;
    float* g = d_G + (long long)c0*NT + col;
    #pragma unroll
    for (int cc = 0; cc < 32; cc++) {
        g[(long long)cc*NT] = fb[(long long)cc*HWP];
    }
}

// ---------- 64x128-tile SGEMM:  Y[m][col] = act(bias[m] + sum_k W[m][k] X[k][col]) ----------
template<bool RELU>
__global__ void k_gemm(const float* __restrict__ W, const float* __restrict__ bias,
                       const float* __restrict__ X, float* __restrict__ Y) {
    int m0 = blockIdx.y*64, n0 = blockIdx.x*128;
    __shared__ float As[16][64];     // [k][m]
    __shared__ float Bs[16][128];    // [k][col]
    int t = threadIdx.x;
    int tx = t & 15, ty = t >> 4;    // cols tx*8, rows ty*4
    int am = t >> 2, ak = (t & 3) * 4;
    int bk = t >> 4, bc = (t & 15) * 8;
    float acc[4][8] = {};
    for (int kk = 0; kk < NC; kk += 16) {
        float4 av = *(const float4*)&W[(m0+am)*NC + kk + ak];
        As[ak+0][am]=av.x; As[ak+1][am]=av.y; As[ak+2][am]=av.z; As[ak+3][am]=av.w;
        *(float4*)&Bs[bk][bc]   = *(const float4*)&X[(kk+bk)*NT + n0 + bc];
        *(float4*)&Bs[bk][bc+4] = *(const float4*)&X[(kk+bk)*NT + n0 + bc + 4];
        __syncthreads();
        #pragma unroll
        for (int k = 0; k < 16; k++) {
            float a[4], bb[8];
            *(float4*)a      = *(float4*)&As[k][ty*4];
            *(float4*)bb     = *(float4*)&Bs[k][tx*8];
            *(float4*)(bb+4) = *(float4*)&Bs[k][tx*8+4];
            #pragma unroll
            for (int r = 0; r < 4; r++)
                #pragma unroll
                for (int q = 0; q < 8; q++)
                    acc[r][q] = fmaf(a[r], bb[q], acc[r][q]);
        }
        __syncthreads();
    }
    #pragma unroll
    for (int r = 0; r < 4; r++) {
        float bv = bias[m0 + ty*4 + r];
        float4 v0, v1;
        float vv[8];
        #pragma unroll
        for (int q = 0; q < 8; q++) {
            float v = acc[r][q] + bv;
            if (RELU) v = fmaxf(v, 0.f);
            vv[q] = v;
        }
        v0 = *(float4*)vv; v1 = *(float4*)(vv+4);
        float* yp = &Y[(m0+ty*4+r)*NT + n0 + tx*8];
        *(float4*)yp = v0; *(float4*)(yp+4) = v1;
    }
}

// ---------- fused attention head: sigmoid(wa2 . relu(wa1 x + ba1) + ba2) ----------
__global__ void k_attn(const float* __restrict__ wa1, const float* __restrict__ ba1,
                       const float* __restrict__ wa2, const float* __restrict__ ba2,
                       const float* __restrict__ X) {
    int n0 = blockIdx.x * 128;
    __shared__ float As[16][64];
    __shared__ float Bs[16][128];
    __shared__ float stage[8][128];
    int t = threadIdx.x, tx = t & 15, ty = t >> 4;
    int am = t >> 2, ak = (t & 3) * 4;
    int bk = t >> 4, bc = (t & 15) * 8;
    float acc[4][8] = {};
    for (int kk = 0; kk < NC; kk += 16) {
        float4 av = *(const float4*)&wa1[am*NC + kk + ak];
        As[ak+0][am]=av.x; As[ak+1][am]=av.y; As[ak+2][am]=av.z; As[ak+3][am]=av.w;
        *(float4*)&Bs[bk][bc]   = *(const float4*)&X[(kk+bk)*NT + n0 + bc];
        *(float4*)&Bs[bk][bc+4] = *(const float4*)&X[(kk+bk)*NT + n0 + bc + 4];
        __syncthreads();
        #pragma unroll
        for (int k = 0; k < 16; k++) {
            float a[4], bb[8];
            *(float4*)a      = *(float4*)&As[k][ty*4];
            *(float4*)bb     = *(float4*)&Bs[k][tx*8];
            *(float4*)(bb+4) = *(float4*)&Bs[k][tx*8+4];
            #pragma unroll
            for (int r = 0; r < 4; r++)
                #pragma unroll
                for (int q = 0; q < 8; q++)
                    acc[r][q] = fmaf(a[r], bb[q], acc[r][q]);
        }
        __syncthreads();
    }
    float part[8] = {};
    #pragma unroll
    for (int r = 0; r < 4; r++) {
        int m = ty*4 + r;
        float bm = ba1[m], wm = wa2[m];
        #pragma unroll
        for (int q = 0; q < 8; q++)
            part[q] = fmaf(wm, fmaxf(acc[r][q] + bm, 0.f), part[q]);
    }
    #pragma unroll
    for (int q = 0; q < 8; q++) part[q] += __shfl_xor_sync(0xffffffffu, part[q], 16);
    int w = t >> 5;
    if ((t & 31) < 16) {
        #pragma unroll
        for (int q = 0; q < 8; q++) stage[w][tx*8+q] = part[q];
    }
    __syncthreads();
    if (t < 128) {
        float sm = 0.f;
        #pragma unroll
        for (int ww = 0; ww < 8; ww++) sm += stage[ww][t];
        float z = sm + ba2[0];
        d_attn[n0 + t] = 1.f / (1.f + expf(-z));
    }
}

// ---------- reciprocal L2 norms of P columns ----------
__global__ void k_rnorm() {
    int col = blockIdx.x*256 + threadIdx.x;
    float ss = 0.f;
    #pragma unroll 8
    for (int c = 0; c < NC; c++) { float v = d_P[c*NT + col]; ss = fmaf(v, v, ss); }
    d_rnorm[col] = 1.f / fmaxf(sqrtf(ss), 1e-12f);
}

// ---------- fused sim + contrastive reductions, symmetric tile enumeration ----------
__global__ void k_sim() {
    int b = blockIdx.z;
    int pid = blockIdx.x;                // 0..35 -> (I<=J) pair of 128-tiles
    int I = 0, rem = pid;
    while (rem >= (8 - I)) { rem -= (8 - I); I++; }
    int J = I + rem;
    int i0 = I*128, j0 = J*128;
    bool diag = (I == J);
    const float* Pb = d_P + b*NS;

    __shared__ float As[16][128], Bs[16][128];
    __shared__ int   spI[128], spJ[128], seI[128], seJ[128];
    __shared__ float wI[128], wJ[128], rnI[128], rnJ[128];
    __shared__ float stage[3][8][128];

    int t = threadIdx.x;
    int tx = t & 15, ty = t >> 4;        // cols tx*8, rows ty*8
    if (t < 128) {
        int ci = b*NS + i0 + t;
        spI[t] = d_spv[ci]; seI[t] = d_sel[ci]; wI[t] = d_attn[ci]; rnI[t] = d_rnorm[ci];
    } else {
        int u = t - 128;
        int cj = b*NS + j0 + u;
        spJ[u] = d_spv[cj]; seJ[u] = d_sel[cj]; wJ[u] = d_attn[cj]; rnJ[u] = d_rnorm[cj];
    }

    int k_l = t >> 4, c0 = (t & 15) * 8;
    float acc[8][8] = {};
    for (int kk = 0; kk < NC; kk += 16) {
        const float* rowp = Pb + (kk + k_l)*NT;
        *(float4*)&As[k_l][c0]   = *(const float4*)&rowp[i0 + c0];
        *(float4*)&As[k_l][c0+4] = *(const float4*)&rowp[i0 + c0 + 4];
        *(float4*)&Bs[k_l][c0]   = *(const float4*)&rowp[j0 + c0];
        *(float4*)&Bs[k_l][c0+4] = *(const float4*)&rowp[j0 + c0 + 4];
        __syncthreads();
        #pragma unroll
        for (int k = 0; k < 16; k++) {
            float a[8], bb[8];
            *(float4*)a      = *(float4*)&As[k][ty*8];
            *(float4*)(a+4)  = *(float4*)&As[k][ty*8+4];
            *(float4*)bb     = *(float4*)&Bs[k][tx*8];
            *(float4*)(bb+4) = *(float4*)&Bs[k][tx*8+4];
            #pragma unroll
            for (int r = 0; r < 8; r++)
                #pragma unroll
                for (int q = 0; q < 8; q++)
                    acc[r][q] = fmaf(a[r], bb[q], acc[r][q]);
        }
        __syncthreads();
    }

    // epilogue: row-direction (i) stats always; col-direction (j) stats for off-diag tiles
    float colA[8] = {}, colB[8] = {}, colD[8] = {};
    #pragma unroll
    for (int r = 0; r < 8; r++) {
        int il = ty*8 + r, gi = i0 + il;
        int si = seI[il], spi = spI[il];
        float wi = wI[il], ri = rnI[il];
        float rA = 0.f, rB = 0.f, rD = 0.f;
        #pragma unroll
        for (int q = 0; q < 8; q++) {
            int jl = tx*8 + q, gj = j0 + jl;
            float s = acc[r][q] * ri * rnJ[jl];
            float e = __expf(10.0f * s);           // 1/TEMP = 10
            int sj = seJ[jl];
            if (sj) rD += e;
            if (!diag && si) colD[q] += e;
            if (si && sj && (gi != gj) && (spi == spJ[jl]) && (s > 0.7f)) {
                float pw = wi * wJ[jl];
                rB += pw; rA = fmaf(pw, s, rA);
                if (!diag) { colB[q] += pw; colA[q] = fmaf(pw, s, colA[q]); }
            }
        }
        #pragma unroll
        for (int off = 8; off >= 1; off >>= 1) {
            rA += __shfl_down_sync(0xffffffffu, rA, off, 16);
            rB += __shfl_down_sync(0xffffffffu, rB, off, 16);
            rD += __shfl_down_sync(0xffffffffu, rD, off, 16);
        }
        if (tx == 0) {
            atomicAdd(&d_rowA[b*NS + gi], rA);
            atomicAdd(&d_rowB[b*NS + gi], rB);
            atomicAdd(&d_rowD[b*NS + gi], rD);
        }
    }
    if (!diag) {
        int w = t >> 5;
        #pragma unroll
        for (int q = 0; q < 8; q++) {
            colA[q] += __shfl_xor_sync(0xffffffffu, colA[q], 16);
            colB[q] += __shfl_xor_sync(0xffffffffu, colB[q], 16);
            colD[q] += __shfl_xor_sync(0xffffffffu, colD[q], 16);
        }
        if ((t & 31) < 16) {
            #pragma unroll
            for (int q = 0; q < 8; q++) {
                stage[0][w][tx*8+q] = colA[q];
                stage[1][w][tx*8+q] = colB[q];
                stage[2][w][tx*8+q] = colD[q];
            }
        }
        __syncthreads();
        if (t < 128) {
            float a0=0.f, b0=0.f, d0=0.f;
            #pragma unroll
            for (int ww = 0; ww < 8; ww++) {
                a0 += stage[0][ww][t]; b0 += stage[1][ww][t]; d0 += stage[2][ww][t];
            }
            atomicAdd(&d_rowA[b*NS + j0 + t], a0);
            atomicAdd(&d_rowB[b*NS + j0 + t], b0);
            atomicAdd(&d_rowD[b*NS + j0 + t], d0);
        }
    }
}

// ---------- final reduction ----------
__global__ void k_final(float* __restrict__ out) {
    __shared__ float red[256];
    __shared__ float s_num, s_ps;
    int t = threadIdx.x;
    float totLoss = 0.f;
    int nHas = 0;
    for (int b = 0; b < NB; b++) {
        float num = 0.f, ps = 0.f;
        for (int i = t; i < NS; i += 256) {
            float Ai = d_rowA[b*NS+i], Bi = d_rowB[b*NS+i], Di = d_rowD[b*NS+i];
            float ld = logf(Di > 0.f ? Di : 1.f);
            num += Ai * 10.0f - ld * Bi;   // Ai/TEMP
            ps  += Bi;
        }
        red[t] = num; __syncthreads();
        for (int o = 128; o > 0; o >>= 1) { if (t < o) red[t] += red[t+o]; __syncthreads(); }
        if (t == 0) s_num = red[0];
        __syncthreads();
        red[t] = ps; __syncthreads();
        for (int o = 128; o > 0; o >>= 1) { if (t < o) red[t] += red[t+o]; __syncthreads(); }
        if (t == 0) s_ps = red[0];
        __syncthreads();
        if (t == 0) {
            if (s_ps > 0.f) {
                totLoss += -(0.1f/0.07f) * s_num / s_ps;
                nHas++;
            }
        }
        __syncthreads();
    }
    if (t == 0) out[0] = (nHas > 0) ? (totLoss / fmaxf((float)nHas, 1.f)) : 0.f;
}

extern "C" void kernel_launch(void* const* d_in, const int* in_sizes, int n_in,
                              void* d_out, int out_size) {
    const float*     feats  = (const float*)d_in[0];
    const long long* labels = (const long long*)d_in[1];
    const long long* sp     = (const long long*)d_in[2];
    const float*     w1     = (const float*)d_in[3];
    const float*     b1     = (const float*)d_in[4];
    const float*     w2     = (const float*)d_in[5];
    const float*     b2     = (const float*)d_in[6];
    const float*     wa1    = (const float*)d_in[7];
    const float*     ba1    = (const float*)d_in[8];
    const float*     wa2    = (const float*)d_in[9];
    const float*     ba2    = (const float*)d_in[10];
    float* out = (float*)d_out;

    static float* pG = nullptr; static float* pH = nullptr; static float* pP = nullptr;
    if (!pG) {
        cudaGetSymbolAddress((void**)&pG, d_G);
        cudaGetSymbolAddress((void**)&pH, d_H);
        cudaGetSymbolAddress((void**)&pP, d_P);
    }

    k_prep  <<<NB, 1024>>>(labels, sp);
    k_gather<<<dim3(NS/256, NC/32, NB), 256>>>(feats);
    k_gemm<true ><<<dim3(NT/128, NC/64), 256>>>(w1, b1, pG, pH);
    k_attn  <<<dim3(NT/128), 256>>>(wa1, ba1, wa2, ba2, pG);
    k_gemm<false><<<dim3(NT/128, NC/64), 256>>>(w2, b2, pH, pP);
    k_rnorm <<<NT/256, 256>>>();
    k_sim   <<<dim3(36, 1, NB), 256>>>();
    k_final <<<1, 256>>>(out);
}

// round 3
// speedup vs baseline: 2.1208x; 1.3167x over previous
#include <cuda_runtime.h>
#include <math.h>

#define NB 4
#define NC 256
#define HWP 25600
#define NS 1024
#define NT 4096   // NB*NS : all per-sample arrays indexed by col = b*NS + s

// ---------- scratch (static device globals; no allocation) ----------
__device__ float d_G[NC*NT];     // gathered feats   [c][col]
__device__ float d_H[NC*NT];     // hidden           [m][col]
__device__ float d_P[NC*NT];     // projection       [m][col]
__device__ float d_attn[NT];
__device__ float d_ss[NT];       // per-column sum of squares of P
__device__ int   d_idx[NT];
__device__ int   d_sel[NT];
__device__ int   d_spv[NT];
__device__ int   d_vlist[NT];
__device__ int   d_ilist[NT];
__device__ float d_rowA[NT];
__device__ float d_rowB[NT];
__device__ float d_rowD[NT];

// ---------- fused selection: count/scan/fill/compose/zero, one block per batch ----------
__global__ void k_prep(const long long* __restrict__ labels, const long long* __restrict__ sp) {
    int b = blockIdx.x, t = threadIdx.x;          // 1024 threads
    const long long* lb = labels + (long long)b*HWP;
    int base = t*25;
    unsigned flags = 0; int cnt = 0;
    #pragma unroll
    for (int j = 0; j < 25; j++) {
        int f = (lb[base+j] == 1);
        flags |= (unsigned)f << j; cnt += f;
    }
    __shared__ int wsum[32];
    __shared__ int s_nv;
    int lane = t & 31, w = t >> 5;
    int incl = cnt;
    #pragma unroll
    for (int o = 1; o < 32; o <<= 1) {
        int n = __shfl_up_sync(0xffffffffu, incl, o);
        if (lane >= o) incl += n;
    }
    if (lane == 31) wsum[w] = incl;
    __syncthreads();
    if (t < 32) {
        int v = wsum[t]; int inc2 = v;
        #pragma unroll
        for (int o = 1; o < 32; o <<= 1) {
            int n = __shfl_up_sync(0xffffffffu, inc2, o);
            if (t >= o) inc2 += n;
        }
        wsum[t] = inc2 - v;          // exclusive warp offsets
        if (t == 31) s_nv = inc2;    // total valid
    }
    __syncthreads();
    int v_run = (incl - cnt) + wsum[w];   // # valid strictly before my range
    #pragma unroll
    for (int j = 0; j < 25; j++) {
        int p = base + j;
        if ((flags >> j) & 1u) {
            if (v_run < NS) d_vlist[b*NS + v_run] = p;
            v_run++;
        } else {
            int ir = p - v_run;             // invalid rank
            if (ir < NS) d_ilist[b*NS + ir] = p;
        }
    }
    __syncthreads();
    int nv = s_nv; if (nv > NS) nv = NS;
    int s = t;
    int p, se;
    if (s < nv) { p = d_vlist[b*NS + s];        se = 1; }
    else        { p = d_ilist[b*NS + (s - nv)]; se = 0; }
    int col = b*NS + s;
    d_idx[col] = p;
    d_sel[col] = se;
    d_spv[col] = (int)sp[(long long)b*HWP + p];
    d_rowA[col] = 0.f; d_rowB[col] = 0.f; d_rowD[col] = 0.f; d_ss[col] = 0.f;
}

// ---------- gather feats -> G[c][col] ----------
__global__ void k_gather(const float* __restrict__ feats) {
    int t = threadIdx.x;
    int s = blockIdx.x*256 + t;      // 0..1023
    int b = blockIdx.z;
    int c0 = blockIdx.y*32;
    int col = b*NS + s;
    int p = d_idx[col];
    const float* fb = feats + ((long long)b*NC + c0)*HWP + p;
    float* g = d_G + (long long)c0*NT + col;
    #pragma unroll
    for (int cc = 0; cc < 32; cc++) {
        g[(long long)cc*NT] = __ldg(&fb[(long long)cc*HWP]);
    }
}

// ---------- 64x128-tile SGEMM with register-prefetch double buffering ----------
// Y[m][col] = act(bias[m] + sum_k W[m][k] X[k][col]);  NORM: accumulate column sumsq of Y into d_ss
template<bool RELU, bool NORM>
__global__ void k_gemm(const float* __restrict__ W, const float* __restrict__ bias,
                       const float* __restrict__ X, float* __restrict__ Y) {
    int m0 = blockIdx.y*64, n0 = blockIdx.x*128;
    __shared__ float As[16][68];     // [k][m], padded stride (16B aligned, bank-shifted)
    __shared__ float Bs[16][132];    // [k][col]
    __shared__ float s_ss[128];
    int t = threadIdx.x;
    int tx = t & 15, ty = t >> 4;    // cols tx*8, rows ty*4
    int am = t >> 2, ak = (t & 3) * 4;
    int bk = t >> 4, bc = (t & 15) * 8;
    if (NORM && t < 128) s_ss[t] = 0.f;
    float4 pa  = *(const float4*)&W[(m0+am)*NC + ak];
    float4 pb0 = *(const float4*)&X[bk*NT + n0 + bc];
    float4 pb1 = *(const float4*)&X[bk*NT + n0 + bc + 4];
    float acc[4][8] = {};
    for (int kk = 0; kk < NC; kk += 16) {
        As[ak+0][am]=pa.x; As[ak+1][am]=pa.y; As[ak+2][am]=pa.z; As[ak+3][am]=pa.w;
        *(float4*)&Bs[bk][bc]   = pb0;
        *(float4*)&Bs[bk][bc+4] = pb1;
        __syncthreads();
        if (kk + 16 < NC) {
            pa  = *(const float4*)&W[(m0+am)*NC + kk+16 + ak];
            pb0 = *(const float4*)&X[(kk+16+bk)*NT + n0 + bc];
            pb1 = *(const float4*)&X[(kk+16+bk)*NT + n0 + bc + 4];
        }
        #pragma unroll
        for (int k = 0; k < 16; k++) {
            float a[4], bb[8];
            *(float4*)a      = *(float4*)&As[k][ty*4];
            *(float4*)bb     = *(float4*)&Bs[k][tx*8];
            *(float4*)(bb+4) = *(float4*)&Bs[k][tx*8+4];
            #pragma unroll
            for (int r = 0; r < 4; r++)
                #pragma unroll
                for (int q = 0; q < 8; q++)
                    acc[r][q] = fmaf(a[r], bb[q], acc[r][q]);
        }
        __syncthreads();
    }
    float ssq[8] = {};
    #pragma unroll
    for (int r = 0; r < 4; r++) {
        float bv = bias[m0 + ty*4 + r];
        float vv[8];
        #pragma unroll
        for (int q = 0; q < 8; q++) {
            float v = acc[r][q] + bv;
            if (RELU) v = fmaxf(v, 0.f);
            vv[q] = v;
            if (NORM) ssq[q] = fmaf(v, v, ssq[q]);
        }
        float* yp = &Y[(m0+ty*4+r)*NT + n0 + tx*8];
        *(float4*)yp = *(float4*)vv; *(float4*)(yp+4) = *(float4*)(vv+4);
    }
    if (NORM) {
        #pragma unroll
        for (int q = 0; q < 8; q++) atomicAdd(&s_ss[tx*8+q], ssq[q]);
        __syncthreads();
        if (t < 128) atomicAdd(&d_ss[n0 + t], s_ss[t]);
    }
}

// ---------- attention head, 32-col tiles (grid=128, full wave) ----------
__global__ void k_attn(const float* __restrict__ wa1, const float* __restrict__ ba1,
                       const float* __restrict__ wa2, const float* __restrict__ ba2,
                       const float* __restrict__ X) {
    int n0 = blockIdx.x * 32;
    __shared__ float As[16][68];     // [k][m], m=0..63
    __shared__ float Bs[16][36];     // [k][col], col=0..31
    __shared__ float stage[8][32];
    int t = threadIdx.x;
    int c = t & 31;                  // column this thread owns
    int g = t >> 5;                  // row group: rows g*8 .. g*8+7
    int am = t >> 2, ak = (t & 3) * 4;
    int bk = t >> 4, bc = (t & 15) * 2;
    float4 pa  = *(const float4*)&wa1[am*NC + ak];
    float2 pb  = *(const float2*)&X[bk*NT + n0 + bc];
    float acc[8] = {};
    for (int kk = 0; kk < NC; kk += 16) {
        As[ak+0][am]=pa.x; As[ak+1][am]=pa.y; As[ak+2][am]=pa.z; As[ak+3][am]=pa.w;
        *(float2*)&Bs[bk][bc] = pb;
        __syncthreads();
        if (kk + 16 < NC) {
            pa = *(const float4*)&wa1[am*NC + kk+16 + ak];
            pb = *(const float2*)&X[(kk+16+bk)*NT + n0 + bc];
        }
        #pragma unroll
        for (int k = 0; k < 16; k++) {
            float bv = Bs[k][c];
            #pragma unroll
            for (int r = 0; r < 8; r++)
                acc[r] = fmaf(As[k][g*8+r], bv, acc[r]);
        }
        __syncthreads();
    }
    float part = 0.f;
    #pragma unroll
    for (int r = 0; r < 8; r++) {
        int m = g*8 + r;
        part = fmaf(wa2[m], fmaxf(acc[r] + ba1[m], 0.f), part);
    }
    stage[g][c] = part;
    __syncthreads();
    if (t < 32) {
        float sm = 0.f;
        #pragma unroll
        for (int gg = 0; gg < 8; gg++) sm += stage[gg][t];
        float z = sm + ba2[0];
        d_attn[n0 + t] = 1.f / (1.f + expf(-z));
    }
}

// ---------- fused sim + contrastive reductions, symmetric tile enumeration ----------
__global__ void k_sim() {
    int b = blockIdx.z;
    int pid = blockIdx.x;                // 0..35 -> (I<=J) pair of 128-tiles
    int I = 0, rem = pid;
    while (rem >= (8 - I)) { rem -= (8 - I); I++; }
    int J = I + rem;
    int i0 = I*128, j0 = J*128;
    bool diag = (I == J);
    const float* Pb = d_P + b*NS;

    __shared__ float As[16][132], Bs[16][132];
    __shared__ int   spI[128], spJ[128], seI[128], seJ[128];
    __shared__ float wI[128], wJ[128], rnI[128], rnJ[128];
    __shared__ float stage[3][8][128];

    int t = threadIdx.x;
    int tx = t & 15, ty = t >> 4;        // cols tx*8, rows ty*8
    if (t < 128) {
        int ci = b*NS + i0 + t;
        spI[t] = d_spv[ci]; seI[t] = d_sel[ci]; wI[t] = d_attn[ci];
        rnI[t] = 1.f / fmaxf(sqrtf(d_ss[ci]), 1e-12f);
    } else {
        int u = t - 128;
        int cj = b*NS + j0 + u;
        spJ[u] = d_spv[cj]; seJ[u] = d_sel[cj]; wJ[u] = d_attn[cj];
        rnJ[u] = 1.f / fmaxf(sqrtf(d_ss[cj]), 1e-12f);
    }

    int k_l = t >> 4, c0 = (t & 15) * 8;
    const float* rowp = Pb + k_l*NT;
    float4 ra0 = *(const float4*)&rowp[i0 + c0];
    float4 ra1 = *(const float4*)&rowp[i0 + c0 + 4];
    float4 rb0 = *(const float4*)&rowp[j0 + c0];
    float4 rb1 = *(const float4*)&rowp[j0 + c0 + 4];
    float acc[8][8] = {};
    for (int kk = 0; kk < NC; kk += 16) {
        *(float4*)&As[k_l][c0]   = ra0;
        *(float4*)&As[k_l][c0+4] = ra1;
        *(float4*)&Bs[k_l][c0]   = rb0;
        *(float4*)&Bs[k_l][c0+4] = rb1;
        __syncthreads();
        if (kk + 16 < NC) {
            const float* rp = Pb + (kk+16+k_l)*NT;
            ra0 = *(const float4*)&rp[i0 + c0];
            ra1 = *(const float4*)&rp[i0 + c0 + 4];
            rb0 = *(const float4*)&rp[j0 + c0];
            rb1 = *(const float4*)&rp[j0 + c0 + 4];
        }
        #pragma unroll
        for (int k = 0; k < 16; k++) {
            float a[8], bb[8];
            *(float4*)a      = *(float4*)&As[k][ty*8];
            *(float4*)(a+4)  = *(float4*)&As[k][ty*8+4];
            *(float4*)bb     = *(float4*)&Bs[k][tx*8];
            *(float4*)(bb+4) = *(float4*)&Bs[k][tx*8+4];
            #pragma unroll
            for (int r = 0; r < 8; r++)
                #pragma unroll
                for (int q = 0; q < 8; q++)
                    acc[r][q] = fmaf(a[r], bb[q], acc[r][q]);
        }
        __syncthreads();
    }

    // epilogue: row-direction (i) stats always; col-direction (j) stats for off-diag tiles
    float colA[8] = {}, colB[8] = {}, colD[8] = {};
    #pragma unroll
    for (int r = 0; r < 8; r++) {
        int il = ty*8 + r, gi = i0 + il;
        int si = seI[il], spi = spI[il];
        float wi = wI[il], ri = rnI[il];
        float rA = 0.f, rB = 0.f, rD = 0.f;
        #pragma unroll
        for (int q = 0; q < 8; q++) {
            int jl = tx*8 + q, gj = j0 + jl;
            float s = acc[r][q] * ri * rnJ[jl];
            float e = __expf(10.0f * s);           // 1/TEMP = 10
            int sj = seJ[jl];
            if (sj) rD += e;
            if (!diag && si) colD[q] += e;
            if (si && sj && (gi != gj) && (spi == spJ[jl]) && (s > 0.7f)) {
                float pw = wi * wJ[jl];
                rB += pw; rA = fmaf(pw, s, rA);
                if (!diag) { colB[q] += pw; colA[q] = fmaf(pw, s, colA[q]); }
            }
        }
        #pragma unroll
        for (int off = 8; off >= 1; off >>= 1) {
            rA += __shfl_down_sync(0xffffffffu, rA, off, 16);
            rB += __shfl_down_sync(0xffffffffu, rB, off, 16);
            rD += __shfl_down_sync(0xffffffffu, rD, off, 16);
        }
        if (tx == 0) {
            atomicAdd(&d_rowA[b*NS + gi], rA);
            atomicAdd(&d_rowB[b*NS + gi], rB);
            atomicAdd(&d_rowD[b*NS + gi], rD);
        }
    }
    if (!diag) {
        int w = t >> 5;
        #pragma unroll
        for (int q = 0; q < 8; q++) {
            colA[q] += __shfl_xor_sync(0xffffffffu, colA[q], 16);
            colB[q] += __shfl_xor_sync(0xffffffffu, colB[q], 16);
            colD[q] += __shfl_xor_sync(0xffffffffu, colD[q], 16);
        }
        if ((t & 31) < 16) {
            #pragma unroll
            for (int q = 0; q < 8; q++) {
                stage[0][w][tx*8+q] = colA[q];
                stage[1][w][tx*8+q] = colB[q];
                stage[2][w][tx*8+q] = colD[q];
            }
        }
        __syncthreads();
        if (t < 128) {
            float a0=0.f, b0=0.f, d0=0.f;
            #pragma unroll
            for (int ww = 0; ww < 8; ww++) {
                a0 += stage[0][ww][t]; b0 += stage[1][ww][t]; d0 += stage[2][ww][t];
            }
            atomicAdd(&d_rowA[b*NS + j0 + t], a0);
            atomicAdd(&d_rowB[b*NS + j0 + t], b0);
            atomicAdd(&d_rowD[b*NS + j0 + t], d0);
        }
    }
}

// ---------- final reduction ----------
__global__ void k_final(float* __restrict__ out) {
    __shared__ float red[256];
    __shared__ float s_num, s_ps;
    int t = threadIdx.x;
    float totLoss = 0.f;
    int nHas = 0;
    for (int b = 0; b < NB; b++) {
        float num = 0.f, ps = 0.f;
        for (int i = t; i < NS; i += 256) {
            float Ai = d_rowA[b*NS+i], Bi = d_rowB[b*NS+i], Di = d_rowD[b*NS+i];
            float ld = logf(Di > 0.f ? Di : 1.f);
            num += Ai * 10.0f - ld * Bi;   // Ai/TEMP
            ps  += Bi;
        }
        red[t] = num; __syncthreads();
        for (int o = 128; o > 0; o >>= 1) { if (t < o) red[t] += red[t+o]; __syncthreads(); }
        if (t == 0) s_num = red[0];
        __syncthreads();
        red[t] = ps; __syncthreads();
        for (int o = 128; o > 0; o >>= 1) { if (t < o) red[t] += red[t+o]; __syncthreads(); }
        if (t == 0) s_ps = red[0];
        __syncthreads();
        if (t == 0) {
            if (s_ps > 0.f) {
                totLoss += -(0.1f/0.07f) * s_num / s_ps;
                nHas++;
            }
        }
        __syncthreads();
    }
    if (t == 0) out[0] = (nHas > 0) ? (totLoss / fmaxf((float)nHas, 1.f)) : 0.f;
}

extern "C" void kernel_launch(void* const* d_in, const int* in_sizes, int n_in,
                              void* d_out, int out_size) {
    const float*     feats  = (const float*)d_in[0];
    const long long* labels = (const long long*)d_in[1];
    const long long* sp     = (const long long*)d_in[2];
    const float*     w1     = (const float*)d_in[3];
    const float*     b1     = (const float*)d_in[4];
    const float*     w2     = (const float*)d_in[5];
    const float*     b2     = (const float*)d_in[6];
    const float*     wa1    = (const float*)d_in[7];
    const float*     ba1    = (const float*)d_in[8];
    const float*     wa2    = (const float*)d_in[9];
    const float*     ba2    = (const float*)d_in[10];
    float* out = (float*)d_out;

    static float* pG = nullptr; static float* pH = nullptr; static float* pP = nullptr;
    if (!pG) {
        cudaGetSymbolAddress((void**)&pG, d_G);
        cudaGetSymbolAddress((void**)&pH, d_H);
        cudaGetSymbolAddress((void**)&pP, d_P);
    }

    k_prep  <<<NB, 1024>>>(labels, sp);
    k_gather<<<dim3(NS/256, NC/32, NB), 256>>>(feats);
    k_attn  <<<dim3(NT/32), 256>>>(wa1, ba1, wa2, ba2, pG);
    k_gemm<true , false><<<dim3(NT/128, NC/64), 256>>>(w1, b1, pG, pH);
    k_gemm<false, true ><<<dim3(NT/128, NC/64), 256>>>(w2, b2, pH, pP);
    k_sim   <<<dim3(36, 1, NB), 256>>>();
    k_final <<<1, 256>>>(out);
}

// round 4
// speedup vs baseline: 2.2913x; 1.0804x over previous
#include <cuda_runtime.h>
#include <math.h>

#define NB 4
#define NC 256
#define HWP 25600
#define NS 1024
#define NT 4096   // NB*NS : all per-sample arrays indexed by col = b*NS + s

typedef unsigned long long u64;

__device__ __forceinline__ u64 dup2(float v) {
    u64 r; asm("mov.b64 %0, {%1, %1};" : "=l"(r) : "f"(v)); return r;
}
__device__ __forceinline__ void fma2(u64& d, u64 a, u64 b) {
    asm("fma.rn.f32x2 %0, %1, %2, %0;" : "+l"(d) : "l"(a), "l"(b));
}
__device__ __forceinline__ float2 unpk(u64 v) {
    float2 f; asm("mov.b64 {%0, %1}, %2;" : "=f"(f.x), "=f"(f.y) : "l"(v)); return f;
}

// ---------- scratch (static device globals; no allocation) ----------
__device__ float d_G[NC*NT];     // gathered feats   [c][col]
__device__ float d_H[NC*NT];     // hidden           [m][col]
__device__ float d_P[NC*NT];     // projection       [m][col]
__device__ float d_attn[NT];
__device__ float d_ss[NT];       // per-column sum of squares of P
__device__ int   d_idx[NT];
__device__ int   d_sel[NT];
__device__ int   d_spv[NT];
__device__ int   d_vlist[NT];
__device__ int   d_ilist[NT];
__device__ float d_rowA[NT];
__device__ float d_rowB[NT];
__device__ float d_rowD[NT];

// ---------- fused selection ----------
__global__ void k_prep(const long long* __restrict__ labels, const long long* __restrict__ sp) {
    int b = blockIdx.x, t = threadIdx.x;          // 1024 threads
    const long long* lb = labels + (long long)b*HWP;
    int base = t*25;
    unsigned flags = 0; int cnt = 0;
    #pragma unroll
    for (int j = 0; j < 25; j++) {
        int f = (lb[base+j] == 1);
        flags |= (unsigned)f << j; cnt += f;
    }
    __shared__ int wsum[32];
    __shared__ int s_nv;
    int lane = t & 31, w = t >> 5;
    int incl = cnt;
    #pragma unroll
    for (int o = 1; o < 32; o <<= 1) {
        int n = __shfl_up_sync(0xffffffffu, incl, o);
        if (lane >= o) incl += n;
    }
    if (lane == 31) wsum[w] = incl;
    __syncthreads();
    if (t < 32) {
        int v = wsum[t]; int inc2 = v;
        #pragma unroll
        for (int o = 1; o < 32; o <<= 1) {
            int n = __shfl_up_sync(0xffffffffu, inc2, o);
            if (t >= o) inc2 += n;
        }
        wsum[t] = inc2 - v;
        if (t == 31) s_nv = inc2;
    }
    __syncthreads();
    int v_run = (incl - cnt) + wsum[w];
    #pragma unroll
    for (int j = 0; j < 25; j++) {
        int p = base + j;
        if ((flags >> j) & 1u) {
            if (v_run < NS) d_vlist[b*NS + v_run] = p;
            v_run++;
        } else {
            int ir = p - v_run;
            if (ir < NS) d_ilist[b*NS + ir] = p;
        }
    }
    __syncthreads();
    int nv = s_nv; if (nv > NS) nv = NS;
    int s = t;
    int p, se;
    if (s < nv) { p = d_vlist[b*NS + s];        se = 1; }
    else        { p = d_ilist[b*NS + (s - nv)]; se = 0; }
    int col = b*NS + s;
    d_idx[col] = p;
    d_sel[col] = se;
    d_spv[col] = (int)sp[(long long)b*HWP + p];
    d_rowA[col] = 0.f; d_rowB[col] = 0.f; d_rowD[col] = 0.f; d_ss[col] = 0.f;
}

// ---------- gather feats -> G[c][col] ----------
__global__ void k_gather(const float* __restrict__ feats) {
    int t = threadIdx.x;
    int s = blockIdx.x*256 + t;
    int b = blockIdx.z;
    int c0 = blockIdx.y*16;
    int col = b*NS + s;
    int p = d_idx[col];
    const float* fb = feats + ((long long)b*NC + c0)*HWP + p;
    float* g = d_G + (long long)c0*NT + col;
    #pragma unroll
    for (int cc = 0; cc < 16; cc++) {
        g[(long long)cc*NT] = __ldg(&fb[(long long)cc*HWP]);
    }
}

// ---------- 64x64-tile SGEMM body with f32x2 packed FMA ----------
// Y[m][col] = act(bias[m] + sum_k W[m][k] X[k][col]); NORM: accumulate col sumsq into d_ss
template<bool RELU, bool NORM>
__device__ __forceinline__ void gemm_tile(const float* __restrict__ W, const float* __restrict__ bias,
                                          const float* __restrict__ X, float* __restrict__ Y,
                                          int m0, int n0) {
    __shared__ float As[16][68];     // [k][m]
    __shared__ float Bs[16][68];     // [k][col]
    __shared__ float s_ss[64];
    int t = threadIdx.x;
    int tx = t & 15, ty = t >> 4;    // cols tx*4, rows ty*4
    int am = t >> 2, ak = (t & 3) * 4;
    int bk = t >> 4, bc = (t & 15) * 4;
    if (NORM && t < 64) s_ss[t] = 0.f;
    float4 pa = *(const float4*)&W[(m0+am)*NC + ak];
    float4 pb = *(const float4*)&X[bk*NT + n0 + bc];
    u64 acc2[4][2] = {};
    for (int kk = 0; kk < NC; kk += 16) {
        As[ak+0][am]=pa.x; As[ak+1][am]=pa.y; As[ak+2][am]=pa.z; As[ak+3][am]=pa.w;
        *(float4*)&Bs[bk][bc] = pb;
        __syncthreads();
        if (kk + 16 < NC) {
            pa = *(const float4*)&W[(m0+am)*NC + kk+16 + ak];
            pb = *(const float4*)&X[(kk+16+bk)*NT + n0 + bc];
        }
        #pragma unroll
        for (int k = 0; k < 16; k++) {
            float4 a4 = *(float4*)&As[k][ty*4];
            ulonglong2 bp = *(ulonglong2*)&Bs[k][tx*4];
            u64 ad[4];
            ad[0] = dup2(a4.x); ad[1] = dup2(a4.y); ad[2] = dup2(a4.z); ad[3] = dup2(a4.w);
            #pragma unroll
            for (int r = 0; r < 4; r++) {
                fma2(acc2[r][0], ad[r], bp.x);
                fma2(acc2[r][1], ad[r], bp.y);
            }
        }
        __syncthreads();
    }
    float ssq[4] = {};
    #pragma unroll
    for (int r = 0; r < 4; r++) {
        float bv = bias[m0 + ty*4 + r];
        float2 c01 = unpk(acc2[r][0]);
        float2 c23 = unpk(acc2[r][1]);
        float vv[4] = {c01.x + bv, c01.y + bv, c23.x + bv, c23.y + bv};
        #pragma unroll
        for (int q = 0; q < 4; q++) {
            if (RELU) vv[q] = fmaxf(vv[q], 0.f);
            if (NORM) ssq[q] = fmaf(vv[q], vv[q], ssq[q]);
        }
        *(float4*)&Y[(m0+ty*4+r)*NT + n0 + tx*4] = *(float4*)vv;
    }
    if (NORM) {
        #pragma unroll
        for (int q = 0; q < 4; q++) atomicAdd(&s_ss[tx*4+q], ssq[q]);
        __syncthreads();
        if (t < 64) atomicAdd(&d_ss[n0 + t], s_ss[t]);
    }
}

// ---------- attention tile: 32 cols, 256 threads ----------
__device__ __forceinline__ void attn_tile(const float* __restrict__ wa1, const float* __restrict__ ba1,
                                          const float* __restrict__ wa2, const float* __restrict__ ba2,
                                          const float* __restrict__ X, int n0) {
    __shared__ float Aa[16][68];     // [k][m], m 0..63
    __shared__ float Ba[16][36];     // [k][col], col 0..31
    __shared__ float stg[8][32];
    int t = threadIdx.x;
    int c = t & 31, g = t >> 5;      // col c, rows g*8..g*8+7
    int am = t >> 2, ak = (t & 3) * 4;
    int bk = t >> 4, bc = (t & 15) * 2;
    float4 pa = *(const float4*)&wa1[am*NC + ak];
    float2 pb = *(const float2*)&X[bk*NT + n0 + bc];
    float acc[8] = {};
    for (int kk = 0; kk < NC; kk += 16) {
        Aa[ak+0][am]=pa.x; Aa[ak+1][am]=pa.y; Aa[ak+2][am]=pa.z; Aa[ak+3][am]=pa.w;
        *(float2*)&Ba[bk][bc] = pb;
        __syncthreads();
        if (kk + 16 < NC) {
            pa = *(const float4*)&wa1[am*NC + kk+16 + ak];
            pb = *(const float2*)&X[(kk+16+bk)*NT + n0 + bc];
        }
        #pragma unroll
        for (int k = 0; k < 16; k++) {
            float bv = Ba[k][c];
            #pragma unroll
            for (int r = 0; r < 8; r++)
                acc[r] = fmaf(Aa[k][g*8+r], bv, acc[r]);
        }
        __syncthreads();
    }
    float part = 0.f;
    #pragma unroll
    for (int r = 0; r < 8; r++) {
        int m = g*8 + r;
        part = fmaf(wa2[m], fmaxf(acc[r] + ba1[m], 0.f), part);
    }
    stg[g][c] = part;
    __syncthreads();
    if (t < 32) {
        float sm = 0.f;
        #pragma unroll
        for (int gg = 0; gg < 8; gg++) sm += stg[gg][t];
        float z = sm + ba2[0];
        d_attn[n0 + t] = 1.f / (1.f + expf(-z));
    }
}

// ---------- fused gemm1 + attn in one launch ----------
__global__ __launch_bounds__(256) void k_g1a(const float* __restrict__ w1, const float* __restrict__ b1,
                      const float* __restrict__ wa1, const float* __restrict__ ba1,
                      const float* __restrict__ wa2, const float* __restrict__ ba2,
                      const float* __restrict__ X, float* __restrict__ Y) {
    if (blockIdx.y < 4) {
        gemm_tile<true, false>(w1, b1, X, Y, blockIdx.y*64, blockIdx.x*64);
    } else {
        int a = (blockIdx.y - 4)*64 + blockIdx.x;   // 0..127
        attn_tile(wa1, ba1, wa2, ba2, X, a*32);
    }
}

__global__ __launch_bounds__(256) void k_gemm2(const float* __restrict__ w2, const float* __restrict__ b2,
                        const float* __restrict__ X, float* __restrict__ Y) {
    gemm_tile<false, true>(w2, b2, X, Y, blockIdx.y*64, blockIdx.x*64);
}

// ---------- fused sim + contrastive reductions, symmetric tiles, 512 threads ----------
__global__ __launch_bounds__(512, 1) void k_sim() {
    int b = blockIdx.z;
    int pid = blockIdx.x;                // 0..35 -> (I<=J) pair of 128-tiles
    int I = 0, rem = pid;
    while (rem >= (8 - I)) { rem -= (8 - I); I++; }
    int J = I + rem;
    int i0 = I*128, j0 = J*128;
    bool diag = (I == J);
    const float* Pb = d_P + b*NS;

    __shared__ float As[16][132], Bs[16][132];
    __shared__ int   spI[128], spJ[128], seI[128], seJ[128];
    __shared__ float wI[128], wJ[128], rnI[128], rnJ[128];
    __shared__ float stage[3][16][128];

    int t = threadIdx.x;
    int tx = t & 15, ty = t >> 4;        // cols tx*8, rows ty*4 (ty 0..31)
    if (t < 128) {
        int ci = b*NS + i0 + t;
        spI[t] = d_spv[ci]; seI[t] = d_sel[ci]; wI[t] = d_attn[ci];
        rnI[t] = 1.f / fmaxf(sqrtf(d_ss[ci]), 1e-12f);
    } else if (t < 256) {
        int u = t - 128;
        int cj = b*NS + j0 + u;
        spJ[u] = d_spv[cj]; seJ[u] = d_sel[cj]; wJ[u] = d_attn[cj];
        rnJ[u] = 1.f / fmaxf(sqrtf(d_ss[cj]), 1e-12f);
    }

    int k_l = t >> 5, c0 = (t & 31) * 4;
    float4 ra = *(const float4*)&Pb[k_l*NT + i0 + c0];
    float4 rb = *(const float4*)&Pb[k_l*NT + j0 + c0];
    u64 acc2[4][4] = {};
    for (int kk = 0; kk < NC; kk += 16) {
        *(float4*)&As[k_l][c0] = ra;
        *(float4*)&Bs[k_l][c0] = rb;
        __syncthreads();
        if (kk + 16 < NC) {
            const float* rp = Pb + (kk+16+k_l)*NT;
            ra = *(const float4*)&rp[i0 + c0];
            rb = *(const float4*)&rp[j0 + c0];
        }
        #pragma unroll
        for (int k = 0; k < 16; k++) {
            float4 a4 = *(float4*)&As[k][ty*4];
            ulonglong2 bp0 = *(ulonglong2*)&Bs[k][tx*8];
            ulonglong2 bp1 = *(ulonglong2*)&Bs[k][tx*8+4];
            u64 ad[4];
            ad[0] = dup2(a4.x); ad[1] = dup2(a4.y); ad[2] = dup2(a4.z); ad[3] = dup2(a4.w);
            #pragma unroll
            for (int r = 0; r < 4; r++) {
                fma2(acc2[r][0], ad[r], bp0.x);
                fma2(acc2[r][1], ad[r], bp0.y);
                fma2(acc2[r][2], ad[r], bp1.x);
                fma2(acc2[r][3], ad[r], bp1.y);
            }
        }
        __syncthreads();
    }

    // epilogue
    float colA[8] = {}, colB[8] = {}, colD[8] = {};
    #pragma unroll
    for (int r = 0; r < 4; r++) {
        int il = ty*4 + r, gi = i0 + il;
        int si = seI[il], spi = spI[il];
        float wi = wI[il], ri = rnI[il];
        float sv[8];
        #pragma unroll
        for (int cp = 0; cp < 4; cp++) {
            float2 p2 = unpk(acc2[r][cp]);
            sv[cp*2] = p2.x; sv[cp*2+1] = p2.y;
        }
        float rA = 0.f, rB = 0.f, rD = 0.f;
        #pragma unroll
        for (int q = 0; q < 8; q++) {
            int jl = tx*8 + q, gj = j0 + jl;
            float s = sv[q] * ri * rnJ[jl];
            float e = __expf(10.0f * s);           // 1/TEMP = 10
            int sj = seJ[jl];
            if (sj) rD += e;
            if (!diag && si) colD[q] += e;
            if (si && sj && (gi != gj) && (spi == spJ[jl]) && (s > 0.7f)) {
                float pw = wi * wJ[jl];
                rB += pw; rA = fmaf(pw, s, rA);
                if (!diag) { colB[q] += pw; colA[q] = fmaf(pw, s, colA[q]); }
            }
        }
        #pragma unroll
        for (int off = 8; off >= 1; off >>= 1) {
            rA += __shfl_down_sync(0xffffffffu, rA, off, 16);
            rB += __shfl_down_sync(0xffffffffu, rB, off, 16);
            rD += __shfl_down_sync(0xffffffffu, rD, off, 16);
        }
        if ((t & 15) == 0) {
            atomicAdd(&d_rowA[b*NS + gi], rA);
            atomicAdd(&d_rowB[b*NS + gi], rB);
            atomicAdd(&d_rowD[b*NS + gi], rD);
        }
    }
    if (!diag) {
        int w = t >> 5;      // 0..15
        #pragma unroll
        for (int q = 0; q < 8; q++) {
            colA[q] += __shfl_xor_sync(0xffffffffu, colA[q], 16);
            colB[q] += __shfl_xor_sync(0xffffffffu, colB[q], 16);
            colD[q] += __shfl_xor_sync(0xffffffffu, colD[q], 16);
        }
        if ((t & 31) < 16) {
            #pragma unroll
            for (int q = 0; q < 8; q++) {
                stage[0][w][tx*8+q] = colA[q];
                stage[1][w][tx*8+q] = colB[q];
                stage[2][w][tx*8+q] = colD[q];
            }
        }
        __syncthreads();
        if (t < 128) {
            float a0=0.f, b0=0.f, d0=0.f;
            #pragma unroll
            for (int ww = 0; ww < 16; ww++) {
                a0 += stage[0][ww][t]; b0 += stage[1][ww][t]; d0 += stage[2][ww][t];
            }
            atomicAdd(&d_rowA[b*NS + j0 + t], a0);
            atomicAdd(&d_rowB[b*NS + j0 + t], b0);
            atomicAdd(&d_rowD[b*NS + j0 + t], d0);
        }
    }
}

// ---------- final reduction ----------
__global__ void k_final(float* __restrict__ out) {
    __shared__ float red[256];
    __shared__ float s_num, s_ps;
    int t = threadIdx.x;
    float totLoss = 0.f;
    int nHas = 0;
    for (int b = 0; b < NB; b++) {
        float num = 0.f, ps = 0.f;
        for (int i = t; i < NS; i += 256) {
            float Ai = d_rowA[b*NS+i], Bi = d_rowB[b*NS+i], Di = d_rowD[b*NS+i];
            float ld = logf(Di > 0.f ? Di : 1.f);
            num += Ai * 10.0f - ld * Bi;
            ps  += Bi;
        }
        red[t] = num; __syncthreads();
        for (int o = 128; o > 0; o >>= 1) { if (t < o) red[t] += red[t+o]; __syncthreads(); }
        if (t == 0) s_num = red[0];
        __syncthreads();
        red[t] = ps; __syncthreads();
        for (int o = 128; o > 0; o >>= 1) { if (t < o) red[t] += red[t+o]; __syncthreads(); }
        if (t == 0) s_ps = red[0];
        __syncthreads();
        if (t == 0) {
            if (s_ps > 0.f) {
                totLoss += -(0.1f/0.07f) * s_num / s_ps;
                nHas++;
            }
        }
        __syncthreads();
    }
    if (t == 0) out[0] = (nHas > 0) ? (totLoss / fmaxf((float)nHas, 1.f)) : 0.f;
}

extern "C" void kernel_launch(void* const* d_in, const int* in_sizes, int n_in,
                              void* d_out, int out_size) {
    const float*     feats  = (const float*)d_in[0];
    const long long* labels = (const long long*)d_in[1];
    const long long* sp     = (const long long*)d_in[2];
    const float*     w1     = (const float*)d_in[3];
    const float*     b1     = (const float*)d_in[4];
    const float*     w2     = (const float*)d_in[5];
    const float*     b2     = (const float*)d_in[6];
    const float*     wa1    = (const float*)d_in[7];
    const float*     ba1    = (const float*)d_in[8];
    const float*     wa2    = (const float*)d_in[9];
    const float*     ba2    = (const float*)d_in[10];
    float* out = (float*)d_out;

    static float* pG = nullptr; static float* pH = nullptr; static float* pP = nullptr;
    if (!pG) {
        cudaGetSymbolAddress((void**)&pG, d_G);
        cudaGetSymbolAddress((void**)&pH, d_H);
        cudaGetSymbolAddress((void**)&pP, d_P);
    }

    k_prep  <<<NB, 1024>>>(labels, sp);
    k_gather<<<dim3(NS/256, NC/16, NB), 256>>>(feats);
    k_g1a   <<<dim3(64, 6), 256>>>(w1, b1, wa1, ba1, wa2, ba2, pG, pH);
    k_gemm2 <<<dim3(64, 4), 256>>>(w2, b2, pH, pP);
    k_sim   <<<dim3(36, 1, NB), 512>>>();
    k_final <<<1, 256>>>(out);
}

// round 5
// speedup vs baseline: 2.4385x; 1.0642x over previous
#include <cuda_runtime.h>
#include <math.h>

#define NB 4
#define NC 256
#define HWP 25600
#define NS 1024
#define NT 4096   // NB*NS

typedef unsigned long long u64;

__device__ __forceinline__ u64 dup2(float v) {
    u64 r; asm("mov.b64 %0, {%1, %1};" : "=l"(r) : "f"(v)); return r;
}
__device__ __forceinline__ void fma2(u64& d, u64 a, u64 b) {
    asm("fma.rn.f32x2 %0, %1, %2, %0;" : "+l"(d) : "l"(a), "l"(b));
}
__device__ __forceinline__ float2 unpk(u64 v) {
    float2 f; asm("mov.b64 {%0, %1}, %2;" : "=f"(f.x), "=f"(f.y) : "l"(v)); return f;
}

// ---------- scratch ----------
__device__ float d_G[NC*NT];
__device__ float d_H[NC*NT];
__device__ float d_P[NC*NT];
__device__ float d_attn[NT];
__device__ float d_ss[NT];
__device__ int   d_idx[NT];
__device__ int   d_sel[NT];
__device__ int   d_spv[NT];
__device__ int   d_vlist[NT];
__device__ int   d_ilist[NT];
__device__ float d_rowA[NT];
__device__ float d_rowB[NT];
__device__ float d_rowD[NT];

// ---------- fused selection ----------
__global__ void k_prep(const long long* __restrict__ labels, const long long* __restrict__ sp) {
    int b = blockIdx.x, t = threadIdx.x;          // 1024 threads
    const long long* lb = labels + (long long)b*HWP;
    int base = t*25;
    unsigned flags = 0; int cnt = 0;
    #pragma unroll
    for (int j = 0; j < 25; j++) {
        int f = (lb[base+j] == 1);
        flags |= (unsigned)f << j; cnt += f;
    }
    __shared__ int wsum[32];
    __shared__ int s_nv;
    int lane = t & 31, w = t >> 5;
    int incl = cnt;
    #pragma unroll
    for (int o = 1; o < 32; o <<= 1) {
        int n = __shfl_up_sync(0xffffffffu, incl, o);
        if (lane >= o) incl += n;
    }
    if (lane == 31) wsum[w] = incl;
    __syncthreads();
    if (t < 32) {
        int v = wsum[t]; int inc2 = v;
        #pragma unroll
        for (int o = 1; o < 32; o <<= 1) {
            int n = __shfl_up_sync(0xffffffffu, inc2, o);
            if (t >= o) inc2 += n;
        }
        wsum[t] = inc2 - v;
        if (t == 31) s_nv = inc2;
    }
    __syncthreads();
    int v_run = (incl - cnt) + wsum[w];
    #pragma unroll
    for (int j = 0; j < 25; j++) {
        int p = base + j;
        if ((flags >> j) & 1u) {
            if (v_run < NS) d_vlist[b*NS + v_run] = p;
            v_run++;
        } else {
            int ir = p - v_run;
            if (ir < NS) d_ilist[b*NS + ir] = p;
        }
    }
    __syncthreads();
    int nv = s_nv; if (nv > NS) nv = NS;
    int s = t;
    int p, se;
    if (s < nv) { p = d_vlist[b*NS + s];        se = 1; }
    else        { p = d_ilist[b*NS + (s - nv)]; se = 0; }
    int col = b*NS + s;
    d_idx[col] = p;
    d_sel[col] = se;
    d_spv[col] = (int)sp[(long long)b*HWP + p];
    d_rowA[col] = 0.f; d_rowB[col] = 0.f; d_rowD[col] = 0.f; d_ss[col] = 0.f;
}

// ---------- gather feats -> G[c][col] ----------
__global__ void k_gather(const float* __restrict__ feats) {
    int t = threadIdx.x;
    int s = blockIdx.x*256 + t;
    int b = blockIdx.z;
    int c0 = blockIdx.y*16;
    int col = b*NS + s;
    int p = d_idx[col];
    const float* fb = feats + ((long long)b*NC + c0)*HWP + p;
    float* g = d_G + (long long)c0*NT + col;
    #pragma unroll
    for (int cc = 0; cc < 16; cc++) {
        g[(long long)cc*NT] = __ldg(&fb[(long long)cc*HWP]);
    }
}

// ---------- 64x128-tile SGEMM, 128 threads, 8x8/thread, double-buffered ----------
template<bool RELU, bool NORM>
__device__ __forceinline__ void gemm_tile(const float* __restrict__ W, const float* __restrict__ bias,
                                          const float* __restrict__ X, float* __restrict__ Y,
                                          int m0, int n0) {
    __shared__ float As[2][16][68];      // [stage][k][m 0..63]
    __shared__ float Bs[2][16][132];     // [stage][k][col 0..127]
    __shared__ float s_ss[128];
    int t = threadIdx.x;
    int tx = t & 15, ty = t >> 4;        // cols tx*8, rows ty*8 (ty 0..7)
    int am = t >> 1, ak = (t & 1) * 8;   // A fill: row am, k cols ak..ak+7
    int bk = t >> 3, bc = (t & 7) * 16;  // B fill: k row bk, cols bc..bc+15
    if (NORM) s_ss[t] = 0.f;

    float4 pa0 = *(const float4*)&W[(m0+am)*NC + ak];
    float4 pa1 = *(const float4*)&W[(m0+am)*NC + ak + 4];
    float4 pb0 = *(const float4*)&X[bk*NT + n0 + bc];
    float4 pb1 = *(const float4*)&X[bk*NT + n0 + bc + 4];
    float4 pb2 = *(const float4*)&X[bk*NT + n0 + bc + 8];
    float4 pb3 = *(const float4*)&X[bk*NT + n0 + bc + 12];
    {
        float av[8]; *(float4*)av = pa0; *(float4*)(av+4) = pa1;
        #pragma unroll
        for (int i = 0; i < 8; i++) As[0][ak+i][am] = av[i];
        *(float4*)&Bs[0][bk][bc]    = pb0;
        *(float4*)&Bs[0][bk][bc+4]  = pb1;
        *(float4*)&Bs[0][bk][bc+8]  = pb2;
        *(float4*)&Bs[0][bk][bc+12] = pb3;
    }
    __syncthreads();

    u64 acc2[8][4] = {};
    for (int c = 0; c < 16; c++) {
        int cur = c & 1;
        if (c < 15) {
            int kk = (c+1)*16;
            pa0 = *(const float4*)&W[(m0+am)*NC + kk + ak];
            pa1 = *(const float4*)&W[(m0+am)*NC + kk + ak + 4];
            pb0 = *(const float4*)&X[(kk+bk)*NT + n0 + bc];
            pb1 = *(const float4*)&X[(kk+bk)*NT + n0 + bc + 4];
            pb2 = *(const float4*)&X[(kk+bk)*NT + n0 + bc + 8];
            pb3 = *(const float4*)&X[(kk+bk)*NT + n0 + bc + 12];
        }
        #pragma unroll
        for (int k = 0; k < 16; k++) {
            float4 a0 = *(float4*)&As[cur][k][ty*8];
            float4 a1 = *(float4*)&As[cur][k][ty*8+4];
            ulonglong2 b0 = *(ulonglong2*)&Bs[cur][k][tx*8];
            ulonglong2 b1 = *(ulonglong2*)&Bs[cur][k][tx*8+4];
            u64 ad[8];
            ad[0]=dup2(a0.x); ad[1]=dup2(a0.y); ad[2]=dup2(a0.z); ad[3]=dup2(a0.w);
            ad[4]=dup2(a1.x); ad[5]=dup2(a1.y); ad[6]=dup2(a1.z); ad[7]=dup2(a1.w);
            #pragma unroll
            for (int r = 0; r < 8; r++) {
                fma2(acc2[r][0], ad[r], b0.x);
                fma2(acc2[r][1], ad[r], b0.y);
                fma2(acc2[r][2], ad[r], b1.x);
                fma2(acc2[r][3], ad[r], b1.y);
            }
        }
        if (c < 15) {
            int nxt = cur ^ 1;
            float av[8]; *(float4*)av = pa0; *(float4*)(av+4) = pa1;
            #pragma unroll
            for (int i = 0; i < 8; i++) As[nxt][ak+i][am] = av[i];
            *(float4*)&Bs[nxt][bk][bc]    = pb0;
            *(float4*)&Bs[nxt][bk][bc+4]  = pb1;
            *(float4*)&Bs[nxt][bk][bc+8]  = pb2;
            *(float4*)&Bs[nxt][bk][bc+12] = pb3;
        }
        __syncthreads();
    }

    float ssq[8] = {};
    #pragma unroll
    for (int r = 0; r < 8; r++) {
        float bv = bias[m0 + ty*8 + r];
        float vv[8];
        #pragma unroll
        for (int cp = 0; cp < 4; cp++) {
            float2 p2 = unpk(acc2[r][cp]);
            vv[cp*2] = p2.x + bv; vv[cp*2+1] = p2.y + bv;
        }
        #pragma unroll
        for (int q = 0; q < 8; q++) {
            if (RELU) vv[q] = fmaxf(vv[q], 0.f);
            if (NORM) ssq[q] = fmaf(vv[q], vv[q], ssq[q]);
        }
        float* yp = &Y[(m0+ty*8+r)*NT + n0 + tx*8];
        *(float4*)yp = *(float4*)vv; *(float4*)(yp+4) = *(float4*)(vv+4);
    }
    if (NORM) {
        #pragma unroll
        for (int q = 0; q < 8; q++) atomicAdd(&s_ss[tx*8+q], ssq[q]);
        __syncthreads();
        atomicAdd(&d_ss[n0 + t], s_ss[t]);
    }
}

// ---------- attention tile: 32 cols, 128 threads ----------
__device__ __forceinline__ void attn_tile(const float* __restrict__ wa1, const float* __restrict__ ba1,
                                          const float* __restrict__ wa2, const float* __restrict__ ba2,
                                          const float* __restrict__ X, int n0) {
    __shared__ float Aa[16][68];     // [k][m 0..63]
    __shared__ float Ba[16][36];     // [k][col 0..31]
    __shared__ float stg[4][32];
    int t = threadIdx.x;
    int c = t & 31, g = t >> 5;      // col c, rows g*16 .. g*16+15
    int am = t >> 1, ak = (t & 1) * 8;
    int bk = t >> 2, bc = (t & 3) * 8;   // 16k x 32c / 128 thr = 4? -> bk 0..31 too big
    // fix B fill: 16 rows x 32 cols = 512 elems / 128 threads = 4 per thread
    bk = t >> 3; bc = (t & 7) * 4;
    float4 pa0 = *(const float4*)&wa1[am*NC + ak];
    float4 pa1 = *(const float4*)&wa1[am*NC + ak + 4];
    float4 pb = *(const float4*)&X[bk*NT + n0 + bc];
    float acc[16] = {};
    for (int kk = 0; kk < NC; kk += 16) {
        {
            float av[8]; *(float4*)av = pa0; *(float4*)(av+4) = pa1;
            #pragma unroll
            for (int i = 0; i < 8; i++) Aa[ak+i][am] = av[i];
            *(float4*)&Ba[bk][bc] = pb;
        }
        __syncthreads();
        if (kk + 16 < NC) {
            pa0 = *(const float4*)&wa1[am*NC + kk+16 + ak];
            pa1 = *(const float4*)&wa1[am*NC + kk+16 + ak + 4];
            pb  = *(const float4*)&X[(kk+16+bk)*NT + n0 + bc];
        }
        #pragma unroll
        for (int k = 0; k < 16; k++) {
            float bv = Ba[k][c];
            #pragma unroll
            for (int r = 0; r < 16; r++)
                acc[r] = fmaf(Aa[k][g*16+r], bv, acc[r]);
        }
        __syncthreads();
    }
    float part = 0.f;
    #pragma unroll
    for (int r = 0; r < 16; r++) {
        int m = g*16 + r;
        part = fmaf(wa2[m], fmaxf(acc[r] + ba1[m], 0.f), part);
    }
    stg[g][c] = part;
    __syncthreads();
    if (t < 32) {
        float sm = stg[0][t] + stg[1][t] + stg[2][t] + stg[3][t];
        float z = sm + ba2[0];
        d_attn[n0 + t] = 1.f / (1.f + expf(-z));
    }
}

// ---------- fused gemm1 + attn ----------
__global__ __launch_bounds__(128) void k_g1a(const float* __restrict__ w1, const float* __restrict__ b1,
                      const float* __restrict__ wa1, const float* __restrict__ ba1,
                      const float* __restrict__ wa2, const float* __restrict__ ba2,
                      const float* __restrict__ X, float* __restrict__ Y) {
    if (blockIdx.y < 4) {
        gemm_tile<true, false>(w1, b1, X, Y, blockIdx.y*64, blockIdx.x*128);
    } else {
        int a = (blockIdx.y - 4)*32 + blockIdx.x;   // 0..127
        attn_tile(wa1, ba1, wa2, ba2, X, a*32);
    }
}

__global__ __launch_bounds__(128) void k_gemm2(const float* __restrict__ w2, const float* __restrict__ b2,
                        const float* __restrict__ X, float* __restrict__ Y) {
    gemm_tile<false, true>(w2, b2, X, Y, blockIdx.y*64, blockIdx.x*128);
}

// ---------- fused sim + contrastive reductions, 256 threads, 8x8, double-buffered ----------
__global__ __launch_bounds__(256, 1) void k_sim() {
    int b = blockIdx.z;
    int pid = blockIdx.x;                // 0..35 -> (I<=J)
    int I = 0, rem = pid;
    while (rem >= (8 - I)) { rem -= (8 - I); I++; }
    int J = I + rem;
    int i0 = I*128, j0 = J*128;
    bool diag = (I == J);
    const float* Pb = d_P + b*NS;

    __shared__ float As[2][16][132], Bs[2][16][132];
    __shared__ int   spI[128], spJ[128], seI[128], seJ[128];
    __shared__ float wI[128], wJ[128], rnI[128], rnJ[128];
    __shared__ float stage[3][8][128];

    int t = threadIdx.x;
    int tx = t & 15, ty = t >> 4;        // cols tx*8, rows ty*8 (ty 0..15)
    if (t < 128) {
        int ci = b*NS + i0 + t;
        spI[t] = d_spv[ci]; seI[t] = d_sel[ci]; wI[t] = d_attn[ci];
        rnI[t] = 1.f / fmaxf(sqrtf(d_ss[ci]), 1e-12f);
    } else {
        int u = t - 128;
        int cj = b*NS + j0 + u;
        spJ[u] = d_spv[cj]; seJ[u] = d_sel[cj]; wJ[u] = d_attn[cj];
        rnJ[u] = 1.f / fmaxf(sqrtf(d_ss[cj]), 1e-12f);
    }

    int k_l = t >> 4, c0 = (t & 15) * 8;
    float4 ra0 = *(const float4*)&Pb[k_l*NT + i0 + c0];
    float4 ra1 = *(const float4*)&Pb[k_l*NT + i0 + c0 + 4];
    float4 rb0 = *(const float4*)&Pb[k_l*NT + j0 + c0];
    float4 rb1 = *(const float4*)&Pb[k_l*NT + j0 + c0 + 4];
    *(float4*)&As[0][k_l][c0]   = ra0;
    *(float4*)&As[0][k_l][c0+4] = ra1;
    *(float4*)&Bs[0][k_l][c0]   = rb0;
    *(float4*)&Bs[0][k_l][c0+4] = rb1;
    __syncthreads();

    u64 acc2[8][4] = {};
    for (int c = 0; c < 16; c++) {
        int cur = c & 1;
        if (c < 15) {
            const float* rp = Pb + ((c+1)*16 + k_l)*NT;
            ra0 = *(const float4*)&rp[i0 + c0];
            ra1 = *(const float4*)&rp[i0 + c0 + 4];
            rb0 = *(const float4*)&rp[j0 + c0];
            rb1 = *(const float4*)&rp[j0 + c0 + 4];
        }
        #pragma unroll
        for (int k = 0; k < 16; k++) {
            float4 a0 = *(float4*)&As[cur][k][ty*8];
            float4 a1 = *(float4*)&As[cur][k][ty*8+4];
            ulonglong2 b0 = *(ulonglong2*)&Bs[cur][k][tx*8];
            ulonglong2 b1 = *(ulonglong2*)&Bs[cur][k][tx*8+4];
            u64 ad[8];
            ad[0]=dup2(a0.x); ad[1]=dup2(a0.y); ad[2]=dup2(a0.z); ad[3]=dup2(a0.w);
            ad[4]=dup2(a1.x); ad[5]=dup2(a1.y); ad[6]=dup2(a1.z); ad[7]=dup2(a1.w);
            #pragma unroll
            for (int r = 0; r < 8; r++) {
                fma2(acc2[r][0], ad[r], b0.x);
                fma2(acc2[r][1], ad[r], b0.y);
                fma2(acc2[r][2], ad[r], b1.x);
                fma2(acc2[r][3], ad[r], b1.y);
            }
        }
        if (c < 15) {
            int nxt = cur ^ 1;
            *(float4*)&As[nxt][k_l][c0]   = ra0;
            *(float4*)&As[nxt][k_l][c0+4] = ra1;
            *(float4*)&Bs[nxt][k_l][c0]   = rb0;
            *(float4*)&Bs[nxt][k_l][c0+4] = rb1;
        }
        __syncthreads();
    }

    // epilogue
    float colA[8] = {}, colB[8] = {}, colD[8] = {};
    #pragma unroll
    for (int r = 0; r < 8; r++) {
        int il = ty*8 + r, gi = i0 + il;
        int si = seI[il], spi = spI[il];
        float wi = wI[il], ri = rnI[il];
        float sv[8];
        #pragma unroll
        for (int cp = 0; cp < 4; cp++) {
            float2 p2 = unpk(acc2[r][cp]);
            sv[cp*2] = p2.x; sv[cp*2+1] = p2.y;
        }
        float rA = 0.f, rB = 0.f, rD = 0.f;
        #pragma unroll
        for (int q = 0; q < 8; q++) {
            int jl = tx*8 + q, gj = j0 + jl;
            float s = sv[q] * ri * rnJ[jl];
            float e = __expf(10.0f * s);           // 1/TEMP = 10
            int sj = seJ[jl];
            if (sj) rD += e;
            if (!diag && si) colD[q] += e;
            if (si && sj && (gi != gj) && (spi == spJ[jl]) && (s > 0.7f)) {
                float pw = wi * wJ[jl];
                rB += pw; rA = fmaf(pw, s, rA);
                if (!diag) { colB[q] += pw; colA[q] = fmaf(pw, s, colA[q]); }
            }
        }
        #pragma unroll
        for (int off = 8; off >= 1; off >>= 1) {
            rA += __shfl_down_sync(0xffffffffu, rA, off, 16);
            rB += __shfl_down_sync(0xffffffffu, rB, off, 16);
            rD += __shfl_down_sync(0xffffffffu, rD, off, 16);
        }
        if ((t & 15) == 0) {
            atomicAdd(&d_rowA[b*NS + gi], rA);
            atomicAdd(&d_rowB[b*NS + gi], rB);
            atomicAdd(&d_rowD[b*NS + gi], rD);
        }
    }
    if (!diag) {
        int w = t >> 5;      // 0..7
        #pragma unroll
        for (int q = 0; q < 8; q++) {
            colA[q] += __shfl_xor_sync(0xffffffffu, colA[q], 16);
            colB[q] += __shfl_xor_sync(0xffffffffu, colB[q], 16);
            colD[q] += __shfl_xor_sync(0xffffffffu, colD[q], 16);
        }
        if ((t & 31) < 16) {
            #pragma unroll
            for (int q = 0; q < 8; q++) {
                stage[0][w][tx*8+q] = colA[q];
                stage[1][w][tx*8+q] = colB[q];
                stage[2][w][tx*8+q] = colD[q];
            }
        }
        __syncthreads();
        if (t < 128) {
            float a0=0.f, b0=0.f, d0=0.f;
            #pragma unroll
            for (int ww = 0; ww < 8; ww++) {
                a0 += stage[0][ww][t]; b0 += stage[1][ww][t]; d0 += stage[2][ww][t];
            }
            atomicAdd(&d_rowA[b*NS + j0 + t], a0);
            atomicAdd(&d_rowB[b*NS + j0 + t], b0);
            atomicAdd(&d_rowD[b*NS + j0 + t], d0);
        }
    }
}

// ---------- final reduction ----------
__global__ void k_final(float* __restrict__ out) {
    __shared__ float red[256];
    __shared__ float s_num, s_ps;
    int t = threadIdx.x;
    float totLoss = 0.f;
    int nHas = 0;
    for (int b = 0; b < NB; b++) {
        float num = 0.f, ps = 0.f;
        for (int i = t; i < NS; i += 256) {
            float Ai = d_rowA[b*NS+i], Bi = d_rowB[b*NS+i], Di = d_rowD[b*NS+i];
            float ld = logf(Di > 0.f ? Di : 1.f);
            num += Ai * 10.0f - ld * Bi;
            ps  += Bi;
        }
        red[t] = num; __syncthreads();
        for (int o = 128; o > 0; o >>= 1) { if (t < o) red[t] += red[t+o]; __syncthreads(); }
        if (t == 0) s_num = red[0];
        __syncthreads();
        red[t] = ps; __syncthreads();
        for (int o = 128; o > 0; o >>= 1) { if (t < o) red[t] += red[t+o]; __syncthreads(); }
        if (t == 0) s_ps = red[0];
        __syncthreads();
        if (t == 0) {
            if (s_ps > 0.f) {
                totLoss += -(0.1f/0.07f) * s_num / s_ps;
                nHas++;
            }
        }
        __syncthreads();
    }
    if (t == 0) out[0] = (nHas > 0) ? (totLoss / fmaxf((float)nHas, 1.f)) : 0.f;
}

extern "C" void kernel_launch(void* const* d_in, const int* in_sizes, int n_in,
                              void* d_out, int out_size) {
    const float*     feats  = (const float*)d_in[0];
    const long long* labels = (const long long*)d_in[1];
    const long long* sp     = (const long long*)d_in[2];
    const float*     w1     = (const float*)d_in[3];
    const float*     b1     = (const float*)d_in[4];
    const float*     w2     = (const float*)d_in[5];
    const float*     b2     = (const float*)d_in[6];
    const float*     wa1    = (const float*)d_in[7];
    const float*     ba1    = (const float*)d_in[8];
    const float*     wa2    = (const float*)d_in[9];
    const float*     ba2    = (const float*)d_in[10];
    float* out = (float*)d_out;

    static float* pG = nullptr; static float* pH = nullptr; static float* pP = nullptr;
    if (!pG) {
        cudaGetSymbolAddress((void**)&pG, d_G);
        cudaGetSymbolAddress((void**)&pH, d_H);
        cudaGetSymbolAddress((void**)&pP, d_P);
    }

    k_prep  <<<NB, 1024>>>(labels, sp);
    k_gather<<<dim3(NS/256, NC/16, NB), 256>>>(feats);
    k_g1a   <<<dim3(32, 8), 128>>>(w1, b1, wa1, ba1, wa2, ba2, pG, pH);
    k_gemm2 <<<dim3(32, 4), 128>>>(w2, b2, pH, pP);
    k_sim   <<<dim3(36, 1, NB), 256>>>();
    k_final <<<1, 256>>>(out);
}